// round 15
// baseline (speedup 1.0000x reference)
#include <cuda_runtime.h>
#include <cuda_fp16.h>
#include <cstdint>
#include <cstddef>

#define NMAX 100000
#define EMAX 1600000
#define TOTMAX (EMAX + NMAX)

#if defined(__CUDA_ARCH_FEAT_SM103_ALL) || defined(__CUDA_ARCH_FEAT_SM100_ALL) || \
    defined(__CUDA_ARCH_FEAT_SM101_ALL)
#define HAS_TCGEN05 1
#else
#define HAS_TCGEN05 0
#endif

// ---------------- device scratch ----------
__device__ int    g_indeg[NMAX];
__device__ float  g_dinv[NMAX];
__device__ int    g_rowptr[NMAX + 1];
__device__ int    g_cursor[NMAX];
__device__ int    g_bsum[1024];
__device__ int    g_esrc[TOTMAX];
__device__ float  g_enorm[TOTMAX];
__device__ __half g_bufA[(size_t)NMAX * 128];
__device__ __half g_bufB[(size_t)NMAX * 128];
__device__ __half g_bufT[(size_t)NMAX * 128];
// Pre-split/swizzled W images (exact SMEM byte layout):
// layers 0..2: 128-out, 32768 halves each (hi 16384 | lo 16384); layer 3: 64-out, 16384 halves.
__device__ __align__(16) __half g_wimg[3 * 32768 + 16384];

// ---------------- PTX helpers ----------------
__device__ __forceinline__ uint32_t smem_u32(const void* p) {
    uint32_t a;
    asm("{ .reg .u64 t; cvta.to.shared.u64 t, %1; cvt.u32.u64 %0, t; }" : "=r"(a) : "l"(p));
    return a;
}

#if HAS_TCGEN05
__device__ __forceinline__ uint32_t elect_one() {
    uint32_t pred;
    asm volatile("{\n .reg .pred p;\n elect.sync _|p, 0xFFFFFFFF;\n selp.b32 %0, 1, 0, p;\n}"
                 : "=r"(pred));
    return pred;
}
#define TC_ALLOC(smem_addr, ncols) \
    asm volatile("tcgen05.alloc.cta_group::1.sync.aligned.shared::cta.b32 [%0], %1;" \
                 :: "r"(smem_addr), "r"(ncols) : "memory")
#define TC_DEALLOC(tmem, ncols) \
    asm volatile("tcgen05.dealloc.cta_group::1.sync.aligned.b32 %0, %1;" :: "r"(tmem), "r"(ncols))
#define TC_COMMIT(mbar) \
    asm volatile("tcgen05.commit.cta_group::1.mbarrier::arrive::one.shared::cluster.b64 [%0];" \
                 :: "r"(mbar) : "memory")
#define TC_WAIT_LD() asm volatile("tcgen05.wait::ld.sync.aligned;" ::: "memory")
#define TC_WAIT_ST() asm volatile("tcgen05.wait::st.sync.aligned;" ::: "memory")
#define TC_FENCE_BEFORE() asm volatile("tcgen05.fence::before_thread_sync;" ::: "memory")
#define TC_FENCE_AFTER() asm volatile("tcgen05.fence::after_thread_sync;" ::: "memory")
#define FENCE_ASYNC_SHARED() asm volatile("fence.proxy.async.shared::cta;" ::: "memory")
#define MBAR_INIT(mbar, cnt) \
    asm volatile("mbarrier.init.shared.b64 [%0], %1;" :: "r"(mbar), "r"(cnt) : "memory")
#define MBAR_INVAL(mbar) \
    asm volatile("mbarrier.inval.shared.b64 [%0];" :: "r"(mbar) : "memory")

__device__ __forceinline__ void mbar_wait(uint32_t mbar, uint32_t parity) {
    asm volatile(
        "{\n .reg .pred P1;\n"
        "WAIT_LOOP_%=:\n"
        " mbarrier.try_wait.parity.acquire.cta.shared::cta.b64 P1, [%0], %1, 0x989680;\n"
        " @P1 bra.uni WAIT_DONE_%=;\n"
        " bra.uni WAIT_LOOP_%=;\n"
        "WAIT_DONE_%=:\n}"
        :: "r"(mbar), "r"(parity) : "memory");
}

__device__ __forceinline__ void mma_f16_rs(uint32_t d, uint32_t a_tmem, uint64_t b,
                                           uint32_t idesc, uint32_t en) {
    uint32_t z = 0;
    asm volatile(
        "{\n .reg .pred p;\n setp.ne.u32 p, %5, 0;\n"
        " tcgen05.mma.cta_group::1.kind::f16 [%0], [%1], %2, %3, {%4, %4, %4, %4}, p;\n}"
        :: "r"(d), "r"(a_tmem), "l"(b), "r"(idesc), "r"(z), "r"(en) : "memory");
}

#define LDTM_X32(r, addr) \
    asm volatile( \
        "tcgen05.ld.sync.aligned.32x32b.x32.b32 " \
        "{%0, %1, %2, %3, %4, %5, %6, %7, %8, %9, %10, %11, %12, %13, %14, %15, " \
        " %16, %17, %18, %19, %20, %21, %22, %23, %24, %25, %26, %27, %28, %29, %30, %31}, [%32];" \
        : "=r"((r)[0]),  "=r"((r)[1]),  "=r"((r)[2]),  "=r"((r)[3]), \
          "=r"((r)[4]),  "=r"((r)[5]),  "=r"((r)[6]),  "=r"((r)[7]), \
          "=r"((r)[8]),  "=r"((r)[9]),  "=r"((r)[10]), "=r"((r)[11]), \
          "=r"((r)[12]), "=r"((r)[13]), "=r"((r)[14]), "=r"((r)[15]), \
          "=r"((r)[16]), "=r"((r)[17]), "=r"((r)[18]), "=r"((r)[19]), \
          "=r"((r)[20]), "=r"((r)[21]), "=r"((r)[22]), "=r"((r)[23]), \
          "=r"((r)[24]), "=r"((r)[25]), "=r"((r)[26]), "=r"((r)[27]), \
          "=r"((r)[28]), "=r"((r)[29]), "=r"((r)[30]), "=r"((r)[31]) \
        : "r"(addr))

#define STTM_X32(addr, r) \
    asm volatile( \
        "tcgen05.st.sync.aligned.32x32b.x32.b32 [%0], " \
        "{%1, %2, %3, %4, %5, %6, %7, %8, " \
        " %9, %10, %11, %12, %13, %14, %15, %16, " \
        " %17, %18, %19, %20, %21, %22, %23, %24, " \
        " %25, %26, %27, %28, %29, %30, %31, %32};" \
        :: "r"(addr), \
           "r"((r)[0]),  "r"((r)[1]),  "r"((r)[2]),  "r"((r)[3]), \
           "r"((r)[4]),  "r"((r)[5]),  "r"((r)[6]),  "r"((r)[7]), \
           "r"((r)[8]),  "r"((r)[9]),  "r"((r)[10]), "r"((r)[11]), \
           "r"((r)[12]), "r"((r)[13]), "r"((r)[14]), "r"((r)[15]), \
           "r"((r)[16]), "r"((r)[17]), "r"((r)[18]), "r"((r)[19]), \
           "r"((r)[20]), "r"((r)[21]), "r"((r)[22]), "r"((r)[23]), \
           "r"((r)[24]), "r"((r)[25]), "r"((r)[26]), "r"((r)[27]), \
           "r"((r)[28]), "r"((r)[29]), "r"((r)[30]), "r"((r)[31]) \
        : "memory")

#define STTM_X64(addr, r) \
    asm volatile( \
        "tcgen05.st.sync.aligned.32x32b.x64.b32 [%0], " \
        "{%1, %2, %3, %4, %5, %6, %7, %8, " \
        " %9, %10, %11, %12, %13, %14, %15, %16, " \
        " %17, %18, %19, %20, %21, %22, %23, %24, " \
        " %25, %26, %27, %28, %29, %30, %31, %32, " \
        " %33, %34, %35, %36, %37, %38, %39, %40, " \
        " %41, %42, %43, %44, %45, %46, %47, %48, " \
        " %49, %50, %51, %52, %53, %54, %55, %56, " \
        " %57, %58, %59, %60, %61, %62, %63, %64};" \
        :: "r"(addr), \
           "r"((r)[0]),  "r"((r)[1]),  "r"((r)[2]),  "r"((r)[3]), \
           "r"((r)[4]),  "r"((r)[5]),  "r"((r)[6]),  "r"((r)[7]), \
           "r"((r)[8]),  "r"((r)[9]),  "r"((r)[10]), "r"((r)[11]), \
           "r"((r)[12]), "r"((r)[13]), "r"((r)[14]), "r"((r)[15]), \
           "r"((r)[16]), "r"((r)[17]), "r"((r)[18]), "r"((r)[19]), \
           "r"((r)[20]), "r"((r)[21]), "r"((r)[22]), "r"((r)[23]), \
           "r"((r)[24]), "r"((r)[25]), "r"((r)[26]), "r"((r)[27]), \
           "r"((r)[28]), "r"((r)[29]), "r"((r)[30]), "r"((r)[31]), \
           "r"((r)[32]), "r"((r)[33]), "r"((r)[34]), "r"((r)[35]), \
           "r"((r)[36]), "r"((r)[37]), "r"((r)[38]), "r"((r)[39]), \
           "r"((r)[40]), "r"((r)[41]), "r"((r)[42]), "r"((r)[43]), \
           "r"((r)[44]), "r"((r)[45]), "r"((r)[46]), "r"((r)[47]), \
           "r"((r)[48]), "r"((r)[49]), "r"((r)[50]), "r"((r)[51]), \
           "r"((r)[52]), "r"((r)[53]), "r"((r)[54]), "r"((r)[55]), \
           "r"((r)[56]), "r"((r)[57]), "r"((r)[58]), "r"((r)[59]), \
           "r"((r)[60]), "r"((r)[61]), "r"((r)[62]), "r"((r)[63]) \
        : "memory")

__device__ __forceinline__ uint64_t make_desc(uint32_t addr) {
    const uint64_t base = (uint64_t(2) << 61) | (uint64_t(1) << 46) |
                          (uint64_t(64) << 32) | (uint64_t(1) << 16);
    return base | ((uint64_t)(addr >> 4) & 0x3FFF);
}
#endif  // HAS_TCGEN05

// ---------------- degree count ----------------
__global__ void k_deg_count(const int* __restrict__ ei, int* indeg, int E) {
    int g = blockIdx.x * blockDim.x + threadIdx.x;
    if (g < E) atomicAdd(&indeg[ei[E + g]], 1);
}

// ---------------- scan1 (+ fused dinv) ----------
__global__ void k_scan1(const int* __restrict__ in, int* out, int* bsum,
                        float* dinv, int n) {
    __shared__ int warp_sums[32];
    int g = blockIdx.x * 1024 + threadIdx.x;
    int lane = threadIdx.x & 31;
    int wid = threadIdx.x >> 5;
    int v = 0;
    if (g < n) {
        v = in[g] + 1;
        dinv[g] = rsqrtf((float)v);
    }
    int x = v;
#pragma unroll
    for (int off = 1; off < 32; off <<= 1) {
        int t = __shfl_up_sync(0xFFFFFFFF, x, off);
        if (lane >= off) x += t;
    }
    if (lane == 31) warp_sums[wid] = x;
    __syncthreads();
    if (wid == 0) {
        int s = (lane < 32) ? warp_sums[lane] : 0;
#pragma unroll
        for (int off = 1; off < 32; off <<= 1) {
            int t = __shfl_up_sync(0xFFFFFFFF, s, off);
            if (lane >= off) s += t;
        }
        warp_sums[lane] = s;
    }
    __syncthreads();
    int wbase = (wid > 0) ? warp_sums[wid - 1] : 0;
    if (g < n) out[g] = wbase + x - v;
    if (threadIdx.x == 1023) bsum[blockIdx.x] = wbase + x;
}
__global__ void k_scan2(int* bsum, int nb) {
    __shared__ int warp_sums[32];
    int lane = threadIdx.x & 31;
    int wid = threadIdx.x >> 5;
    int v = (threadIdx.x < nb) ? bsum[threadIdx.x] : 0;
    int x = v;
#pragma unroll
    for (int off = 1; off < 32; off <<= 1) {
        int t = __shfl_up_sync(0xFFFFFFFF, x, off);
        if (lane >= off) x += t;
    }
    if (lane == 31) warp_sums[wid] = x;
    __syncthreads();
    if (wid == 0) {
        int s = (lane < 32) ? warp_sums[lane] : 0;
#pragma unroll
        for (int off = 1; off < 32; off <<= 1) {
            int t = __shfl_up_sync(0xFFFFFFFF, s, off);
            if (lane >= off) s += t;
        }
        warp_sums[lane] = s;
    }
    __syncthreads();
    int wbase = (wid > 0) ? warp_sums[wid - 1] : 0;
    if (threadIdx.x < nb) bsum[threadIdx.x] = wbase + x - v;
}
__global__ void k_scan3(int* rowptr, const int* __restrict__ bsum, int* cursor,
                        int n, int total) {
    int g = blockIdx.x * 1024 + threadIdx.x;
    if (g < n) {
        int r = rowptr[g] + bsum[g >> 10];
        rowptr[g] = r;
        cursor[g] = r;
    }
    if (g == 0) rowptr[n] = total;
}

// ---------------- CSR fill ----------------
__global__ void k_fill(const int* __restrict__ ei, int E, int n,
                       const float* __restrict__ dinv, int* cursor,
                       int* esrc, float* enorm) {
    int g = blockIdx.x * blockDim.x + threadIdx.x;
    if (g < E) {
        int s = ei[g];
        int d = ei[E + g];
        int pos = atomicAdd(&cursor[d], 1);
        esrc[pos] = s;
        enorm[pos] = dinv[s] * dinv[d];
    } else if (g < E + n) {
        int i = g - E;
        int pos = atomicAdd(&cursor[i], 1);
        esrc[pos] = i;
        float dv = dinv[i];
        enorm[pos] = dv * dv;
    }
}

// ---------------- W prep: split+transpose+swizzle ALL layers once ---------
// Writes the exact SMEM byte-image each GEMM needs: hi panel || lo panel,
// blocked SW128 atom layout.  Layers 0..2 at img+L*32768 (halves), layer 3
// (FOUT=64) at img+98304.
__global__ void k_wprep(const float* __restrict__ W1, const float* __restrict__ Wm1,
                        const float* __restrict__ Wm2, const float* __restrict__ W2,
                        __half* __restrict__ img) {
    int g = blockIdx.x * blockDim.x + threadIdx.x;
    const float* W;
    __half* out;
    int FOUT, gg;
    if (g < 6144) {
        int layer = g >> 11;          // /2048
        gg = g & 2047;
        W = (layer == 0) ? W1 : (layer == 1) ? Wm1 : Wm2;
        out = img + layer * 32768;
        FOUT = 128;
    } else if (g < 7168) {
        gg = g - 6144;                // 0..1023 = 64*16 groups
        W = W2;
        out = img + 98304;
        FOUT = 64;
    } else {
        return;
    }
    int r = gg >> 4;
    int k8 = (gg & 15) << 3;
    uint32_t hu[4], lu[4];
#pragma unroll
    for (int j = 0; j < 4; j++) {
        float x0 = W[(size_t)(k8 + 2 * j) * FOUT + r];
        float x1 = W[(size_t)(k8 + 2 * j + 1) * FOUT + r];
        __half h0 = __float2half_rn(x0);
        __half h1 = __float2half_rn(x1);
        float l0 = x0 - __half2float(h0);
        float l1 = x1 - __half2float(h1);
        __half2 hp = __halves2half2(h0, h1);
        __half2 lp = __halves2half2(__float2half_rn(l0), __float2half_rn(l1));
        hu[j] = *reinterpret_cast<uint32_t*>(&hp);
        lu[j] = *reinterpret_cast<uint32_t*>(&lp);
    }
    int atom = (r >> 3) + (k8 >> 6) * (FOUT >> 3);
    uint32_t boff = atom * 1024 + (r & 7) * 128 + (k8 & 63) * 2;
    uint32_t sw = boff ^ ((boff >> 3) & 0x70);
    *(uint4*)((char*)out + sw) = make_uint4(hu[0], hu[1], hu[2], hu[3]);
    *(uint4*)((char*)(out + FOUT * 128) + sw) = make_uint4(lu[0], lu[1], lu[2], lu[3]);
}

#if HAS_TCGEN05
template <int FOUT>
__device__ __forceinline__ void gemm_epilogue(uint32_t tm_d, int bm, int wid, int lane,
                                              __half* __restrict__ C, int n) {
    int row = bm + wid * 32 + lane;
    for (int c0 = 0; c0 < FOUT; c0 += 32) {
        uint32_t r[32];
        LDTM_X32(r, tm_d + c0);
        TC_WAIT_LD();
        if (row < n) {
            __half* dst = &C[(size_t)row * FOUT + c0];
            uint32_t o[16];
#pragma unroll
            for (int j = 0; j < 16; j++) {
                __half2 hp = __halves2half2(
                    __float2half_rn(__uint_as_float(r[2 * j])),
                    __float2half_rn(__uint_as_float(r[2 * j + 1])));
                o[j] = *reinterpret_cast<uint32_t*>(&hp);
            }
#pragma unroll
            for (int j = 0; j < 4; j++)
                *(uint4*)(dst + j * 8) =
                    make_uint4(o[4 * j], o[4 * j + 1], o[4 * j + 2], o[4 * j + 3]);
        }
    }
    TC_FENCE_BEFORE();
}
#endif

// ---------------- GEMM #1: fp32 input, 3-term fp16 split (layer 1) --------
template <int FOUT>
__global__ void __launch_bounds__(256, 1) __cluster_dims__(1, 1, 1) k_gemm_f32(
    const float* __restrict__ A, const __half* __restrict__ wimg,
    const float* __restrict__ W, __half* __restrict__ C, int n) {
#if HAS_TCGEN05
    extern __shared__ char smem[];
    constexpr int BH_OFF = 1024;
    constexpr uint32_t IDESC = (1u << 4) | ((FOUT / 8) << 17) | (8u << 24);

    uint32_t sbase = smem_u32(smem);
    int tid = threadIdx.x;
    int wid = tid >> 5;
    int lane = tid & 31;

    if (wid == 0) TC_ALLOC(sbase, 512);
    if (tid == 0) { MBAR_INIT(sbase + 8, 1); MBAR_INIT(sbase + 16, 1); }
    __syncthreads();
    uint32_t tmem;
    asm volatile("ld.shared.b32 %0, [%1];" : "=r"(tmem) : "r"(sbase));

    // B fill: coalesced copy of the pre-split/swizzled image (hi||lo).
    {
        const uint4* src = (const uint4*)wimg;
        constexpr int T16 = FOUT * 512 / 16;
        for (int i = tid; i < T16; i += 256)
            *(uint4*)(smem + BH_OFF + i * 16) = src[i];
    }
    FENCE_ASYNC_SHARED();
    __syncthreads();

    uint64_t bh = make_desc(sbase + BH_OFF);
    uint64_t bl = make_desc(sbase + BH_OFF + FOUT * 256);
    const uint64_t BCOL = (uint64_t)FOUT * 8;

    int it = 0;
    int prev_bm = 0;
    for (int tile = blockIdx.x; tile * 128 < n; tile += gridDim.x, it++) {
        int p = it & 1;
        int bm = tile * 128;
        uint32_t tm_a = tmem + p * 128;
        uint32_t tm_d = tmem + 256 + p * 128;

        if (tid >= 128) {
            int wg_tid = tid - 128;
            int row = bm + wg_tid;
            const float4* a4 = (const float4*)&A[(size_t)row * 128];
            uint32_t warp_off = (wg_tid >> 5) << 21;
#pragma unroll
            for (int h = 0; h < 2; h++) {
                float4 f[16];
#pragma unroll
                for (int i = 0; i < 16; i++)
                    f[i] = (row < n) ? a4[h * 16 + i] : make_float4(0.f, 0.f, 0.f, 0.f);
                uint32_t v[32];
#pragma unroll
                for (int i = 0; i < 16; i++) {
                    __half2 p0 = __halves2half2(__float2half_rn(f[i].x),
                                                __float2half_rn(f[i].y));
                    __half2 p1 = __halves2half2(__float2half_rn(f[i].z),
                                                __float2half_rn(f[i].w));
                    v[2 * i]     = *reinterpret_cast<uint32_t*>(&p0);
                    v[2 * i + 1] = *reinterpret_cast<uint32_t*>(&p1);
                }
                STTM_X32(tm_a + h * 32 + warp_off, v);
                TC_WAIT_ST();
#pragma unroll
                for (int i = 0; i < 16; i++) {
                    float lx = f[i].x - __half2float(__float2half_rn(f[i].x));
                    float ly = f[i].y - __half2float(__float2half_rn(f[i].y));
                    float lz = f[i].z - __half2float(__float2half_rn(f[i].z));
                    float lw = f[i].w - __half2float(__float2half_rn(f[i].w));
                    __half2 p0 = __halves2half2(__float2half_rn(lx), __float2half_rn(ly));
                    __half2 p1 = __halves2half2(__float2half_rn(lz), __float2half_rn(lw));
                    v[2 * i]     = *reinterpret_cast<uint32_t*>(&p0);
                    v[2 * i + 1] = *reinterpret_cast<uint32_t*>(&p1);
                }
                STTM_X32(tm_a + 64 + h * 32 + warp_off, v);
                TC_WAIT_ST();
            }
            TC_FENCE_BEFORE();
        } else if (it > 0) {
            int q = p ^ 1;
            mbar_wait(sbase + 8 + 8 * q, ((it - 1) >> 1) & 1);
            TC_FENCE_AFTER();
            gemm_epilogue<FOUT>(tmem + 256 + q * 128, prev_bm, wid, lane, C, n);
        }
        __syncthreads();

        if (wid == 0) {
            TC_FENCE_AFTER();
            if (elect_one()) {
#pragma unroll
                for (int t = 0; t < 3; t++) {
                    uint32_t a_base = tm_a + ((t == 2) ? 64 : 0);
                    uint64_t b_base = (t == 1) ? bl : bh;
#pragma unroll
                    for (int k = 0; k < 8; k++) {
                        uint64_t bd = b_base + ((k < 4) ? (uint64_t)(k * 2)
                                                        : BCOL + (uint64_t)((k - 4) * 2));
                        mma_f16_rs(tm_d, a_base + k * 8, bd, IDESC,
                                   (t > 0 || k > 0) ? 1u : 0u);
                    }
                }
                TC_COMMIT(sbase + 8 + 8 * p);
            }
        }
        prev_bm = bm;
    }
    if (it > 0 && wid < 4) {
        int q = (it - 1) & 1;
        mbar_wait(sbase + 8 + 8 * q, ((it - 1) >> 1) & 1);
        TC_FENCE_AFTER();
        gemm_epilogue<FOUT>(tmem + 256 + q * 128, prev_bm, wid, lane, C, n);
    }
    __syncthreads();
    if (tid == 0) { MBAR_INVAL(sbase + 8); MBAR_INVAL(sbase + 16); }
    __syncthreads();
    if (wid == 0) TC_DEALLOC(tmem, 512);
#else
    int tid = threadIdx.x;
    for (int tile = blockIdx.x; tile * 128 < n; tile += gridDim.x) {
        int bm = tile * 128;
        for (int idx = tid; idx < 128 * FOUT; idx += 256) {
            int r = bm + idx / FOUT, c = idx % FOUT;
            if (r < n) {
                float acc = 0.f;
                for (int k = 0; k < 128; k++)
                    acc += A[(size_t)r * 128 + k] * W[(size_t)k * FOUT + c];
                C[(size_t)r * FOUT + c] = __float2half_rn(acc);
            }
        }
    }
#endif
}

// ---------------- GEMM #2: fp16 input, 2-term (layers 2..4) ----------------
template <int FOUT>
__global__ void __launch_bounds__(256, 1) __cluster_dims__(1, 1, 1) k_gemm_f16(
    const __half* __restrict__ A, const __half* __restrict__ wimg,
    const float* __restrict__ W, __half* __restrict__ C, int n) {
#if HAS_TCGEN05
    extern __shared__ char smem[];
    constexpr int BH_OFF = 1024;
    constexpr uint32_t IDESC = (1u << 4) | ((FOUT / 8) << 17) | (8u << 24);

    uint32_t sbase = smem_u32(smem);
    int tid = threadIdx.x;
    int wid = tid >> 5;
    int lane = tid & 31;

    if (wid == 0) TC_ALLOC(sbase, 512);
    if (tid == 0) { MBAR_INIT(sbase + 8, 1); MBAR_INIT(sbase + 16, 1); }
    __syncthreads();
    uint32_t tmem;
    asm volatile("ld.shared.b32 %0, [%1];" : "=r"(tmem) : "r"(sbase));

    {
        const uint4* src = (const uint4*)wimg;
        constexpr int T16 = FOUT * 512 / 16;
        for (int i = tid; i < T16; i += 256)
            *(uint4*)(smem + BH_OFF + i * 16) = src[i];
    }
    FENCE_ASYNC_SHARED();
    __syncthreads();

    uint64_t bh = make_desc(sbase + BH_OFF);
    uint64_t bl = make_desc(sbase + BH_OFF + FOUT * 256);
    const uint64_t BCOL = (uint64_t)FOUT * 8;

    int it = 0;
    int prev_bm = 0;
    for (int tile = blockIdx.x; tile * 128 < n; tile += gridDim.x, it++) {
        int p = it & 1;
        int bm = tile * 128;
        uint32_t tm_a = tmem + p * 64;
        uint32_t tm_d = tmem + 256 + p * 128;

        if (tid >= 128) {
            int wg_tid = tid - 128;
            int row = bm + wg_tid;
            const uint4* a4 = (const uint4*)&A[(size_t)row * 128];
            uint32_t v[64];
#pragma unroll
            for (int i = 0; i < 16; i++) {
                uint4 u = (row < n) ? a4[i] : make_uint4(0, 0, 0, 0);
                v[4 * i] = u.x; v[4 * i + 1] = u.y; v[4 * i + 2] = u.z; v[4 * i + 3] = u.w;
            }
            uint32_t warp_off = (wg_tid >> 5) << 21;
            STTM_X64(tm_a + warp_off, v);
            TC_WAIT_ST();
            TC_FENCE_BEFORE();
        } else if (it > 0) {
            int q = p ^ 1;
            mbar_wait(sbase + 8 + 8 * q, ((it - 1) >> 1) & 1);
            TC_FENCE_AFTER();
            gemm_epilogue<FOUT>(tmem + 256 + q * 128, prev_bm, wid, lane, C, n);
        }
        __syncthreads();

        if (wid == 0) {
            TC_FENCE_AFTER();
            if (elect_one()) {
#pragma unroll
                for (int t = 0; t < 2; t++) {
                    uint64_t b_base = (t == 1) ? bl : bh;
#pragma unroll
                    for (int k = 0; k < 8; k++) {
                        uint64_t bd = b_base + ((k < 4) ? (uint64_t)(k * 2)
                                                        : BCOL + (uint64_t)((k - 4) * 2));
                        mma_f16_rs(tm_d, tm_a + k * 8, bd, IDESC,
                                   (t > 0 || k > 0) ? 1u : 0u);
                    }
                }
                TC_COMMIT(sbase + 8 + 8 * p);
            }
        }
        prev_bm = bm;
    }
    if (it > 0 && wid < 4) {
        int q = (it - 1) & 1;
        mbar_wait(sbase + 8 + 8 * q, ((it - 1) >> 1) & 1);
        TC_FENCE_AFTER();
        gemm_epilogue<FOUT>(tmem + 256 + q * 128, prev_bm, wid, lane, C, n);
    }
    __syncthreads();
    if (tid == 0) { MBAR_INVAL(sbase + 8); MBAR_INVAL(sbase + 16); }
    __syncthreads();
    if (wid == 0) TC_DEALLOC(tmem, 512);
#else
    int tid = threadIdx.x;
    for (int tile = blockIdx.x; tile * 128 < n; tile += gridDim.x) {
        int bm = tile * 128;
        for (int idx = tid; idx < 128 * FOUT; idx += 256) {
            int r = bm + idx / FOUT, c = idx % FOUT;
            if (r < n) {
                float acc = 0.f;
                for (int k = 0; k < 128; k++)
                    acc += __half2float(A[(size_t)r * 128 + k]) * W[(size_t)k * FOUT + c];
                C[(size_t)r * FOUT + c] = __float2half_rn(acc);
            }
        }
    }
#endif
}

// ---------------- aggregation: 8-edge unroll, vector index loads ----------
__global__ void k_agg128h(const __half* __restrict__ t, const int* __restrict__ rowptr,
                          const int* __restrict__ esrc, const float* __restrict__ enorm,
                          const float* __restrict__ bias, __half* __restrict__ out,
                          int n) {
    int w = (blockIdx.x * blockDim.x + threadIdx.x) >> 5;
    if (w >= n) return;
    int lane = threadIdx.x & 31;
    int beg = rowptr[w], end = rowptr[w + 1];
    float ax = 0.f, ay = 0.f, az = 0.f, aw = 0.f;
    int e = beg;
    for (; e < end && (e & 3); e++) {
        int s0 = esrc[e];
        float n0 = enorm[e];
        uint2 u0 = *(const uint2*)&t[(size_t)s0 * 128 + lane * 4];
        float2 a0 = __half22float2(*reinterpret_cast<__half2*>(&u0.x));
        float2 b0 = __half22float2(*reinterpret_cast<__half2*>(&u0.y));
        ax += a0.x * n0; ay += a0.y * n0; az += b0.x * n0; aw += b0.y * n0;
    }
    for (; e + 7 < end; e += 8) {
        int4 s4a = *(const int4*)&esrc[e];
        int4 s4b = *(const int4*)&esrc[e + 4];
        float4 n4a = *(const float4*)&enorm[e];
        float4 n4b = *(const float4*)&enorm[e + 4];
        uint2 u0 = *(const uint2*)&t[(size_t)s4a.x * 128 + lane * 4];
        uint2 u1 = *(const uint2*)&t[(size_t)s4a.y * 128 + lane * 4];
        uint2 u2 = *(const uint2*)&t[(size_t)s4a.z * 128 + lane * 4];
        uint2 u3 = *(const uint2*)&t[(size_t)s4a.w * 128 + lane * 4];
        uint2 u4 = *(const uint2*)&t[(size_t)s4b.x * 128 + lane * 4];
        uint2 u5 = *(const uint2*)&t[(size_t)s4b.y * 128 + lane * 4];
        uint2 u6 = *(const uint2*)&t[(size_t)s4b.z * 128 + lane * 4];
        uint2 u7 = *(const uint2*)&t[(size_t)s4b.w * 128 + lane * 4];
#define ACC(u, nn)                                                             \
        {                                                                      \
            float2 _a = __half22float2(*reinterpret_cast<__half2*>(&(u).x));   \
            float2 _b = __half22float2(*reinterpret_cast<__half2*>(&(u).y));   \
            ax += _a.x * (nn); ay += _a.y * (nn);                              \
            az += _b.x * (nn); aw += _b.y * (nn);                              \
        }
        ACC(u0, n4a.x) ACC(u1, n4a.y) ACC(u2, n4a.z) ACC(u3, n4a.w)
        ACC(u4, n4b.x) ACC(u5, n4b.y) ACC(u6, n4b.z) ACC(u7, n4b.w)
#undef ACC
    }
    for (; e < end; e++) {
        int s0 = esrc[e];
        float n0 = enorm[e];
        uint2 u0 = *(const uint2*)&t[(size_t)s0 * 128 + lane * 4];
        float2 a0 = __half22float2(*reinterpret_cast<__half2*>(&u0.x));
        float2 b0 = __half22float2(*reinterpret_cast<__half2*>(&u0.y));
        ax += a0.x * n0; ay += a0.y * n0; az += b0.x * n0; aw += b0.y * n0;
    }
    float4 b4 = *(const float4*)&bias[lane * 4];
    ax = fmaxf(ax + b4.x, 0.f);
    ay = fmaxf(ay + b4.y, 0.f);
    az = fmaxf(az + b4.z, 0.f);
    aw = fmaxf(aw + b4.w, 0.f);
    __half2 h0 = __halves2half2(__float2half_rn(ax), __float2half_rn(ay));
    __half2 h1 = __halves2half2(__float2half_rn(az), __float2half_rn(aw));
    *(uint2*)&out[(size_t)w * 128 + lane * 4] =
        make_uint2(*reinterpret_cast<uint32_t*>(&h0), *reinterpret_cast<uint32_t*>(&h1));
}

__global__ void k_agg64h(const __half* __restrict__ t, const int* __restrict__ rowptr,
                         const int* __restrict__ esrc, const float* __restrict__ enorm,
                         const float* __restrict__ bias, float* __restrict__ out,
                         int n) {
    int w = (blockIdx.x * blockDim.x + threadIdx.x) >> 5;
    if (w >= n) return;
    int lane = threadIdx.x & 31;
    int beg = rowptr[w], end = rowptr[w + 1];
    float ax = 0.f, ay = 0.f;
    int e = beg;
    for (; e < end && (e & 3); e++) {
        int s0 = esrc[e];
        float n0 = enorm[e];
        uint32_t u0 = *(const uint32_t*)&t[(size_t)s0 * 64 + lane * 2];
        float2 a0 = __half22float2(*reinterpret_cast<__half2*>(&u0));
        ax += a0.x * n0; ay += a0.y * n0;
    }
    for (; e + 7 < end; e += 8) {
        int4 s4a = *(const int4*)&esrc[e];
        int4 s4b = *(const int4*)&esrc[e + 4];
        float4 n4a = *(const float4*)&enorm[e];
        float4 n4b = *(const float4*)&enorm[e + 4];
        uint32_t u0 = *(const uint32_t*)&t[(size_t)s4a.x * 64 + lane * 2];
        uint32_t u1 = *(const uint32_t*)&t[(size_t)s4a.y * 64 + lane * 2];
        uint32_t u2 = *(const uint32_t*)&t[(size_t)s4a.z * 64 + lane * 2];
        uint32_t u3 = *(const uint32_t*)&t[(size_t)s4a.w * 64 + lane * 2];
        uint32_t u4 = *(const uint32_t*)&t[(size_t)s4b.x * 64 + lane * 2];
        uint32_t u5 = *(const uint32_t*)&t[(size_t)s4b.y * 64 + lane * 2];
        uint32_t u6 = *(const uint32_t*)&t[(size_t)s4b.z * 64 + lane * 2];
        uint32_t u7 = *(const uint32_t*)&t[(size_t)s4b.w * 64 + lane * 2];
#define ACC(u, nn)                                                             \
        {                                                                      \
            float2 _a = __half22float2(*reinterpret_cast<__half2*>(&(u)));     \
            ax += _a.x * (nn); ay += _a.y * (nn);                              \
        }
        ACC(u0, n4a.x) ACC(u1, n4a.y) ACC(u2, n4a.z) ACC(u3, n4a.w)
        ACC(u4, n4b.x) ACC(u5, n4b.y) ACC(u6, n4b.z) ACC(u7, n4b.w)
#undef ACC
    }
    for (; e < end; e++) {
        int s0 = esrc[e];
        float n0 = enorm[e];
        uint32_t u0 = *(const uint32_t*)&t[(size_t)s0 * 64 + lane * 2];
        float2 a0 = __half22float2(*reinterpret_cast<__half2*>(&u0));
        ax += a0.x * n0; ay += a0.y * n0;
    }
    float2 b2 = *(const float2*)&bias[lane * 2];
    ax += b2.x; ay += b2.y;
    *(float2*)&out[(size_t)w * 64 + lane * 2] = make_float2(ax, ay);
}

// ---------------- host ----------------
extern "C" void kernel_launch(void* const* d_in, const int* in_sizes, int n_in,
                              void* d_out, int out_size) {
    const float* x   = (const float*)d_in[0];
    const int*   ei  = (const int*)d_in[1];
    const float* W1  = (const float*)d_in[2];
    const float* b1  = (const float*)d_in[3];
    const float* Wm1 = (const float*)d_in[4];
    const float* bm1 = (const float*)d_in[5];
    const float* Wm2 = (const float*)d_in[6];
    const float* bm2 = (const float*)d_in[7];
    const float* W2  = (const float*)d_in[8];
    const float* b2  = (const float*)d_in[9];

    int n = in_sizes[0] / 128;
    int E = in_sizes[1] / 2;

    void* p;
    int *indeg, *rowptr, *cursor, *bsum, *esrc;
    float *dinv, *enorm;
    __half *hA, *hB, *bufT, *wimg;
    cudaGetSymbolAddress(&p, g_indeg);  indeg  = (int*)p;
    cudaGetSymbolAddress(&p, g_dinv);   dinv   = (float*)p;
    cudaGetSymbolAddress(&p, g_rowptr); rowptr = (int*)p;
    cudaGetSymbolAddress(&p, g_cursor); cursor = (int*)p;
    cudaGetSymbolAddress(&p, g_bsum);   bsum   = (int*)p;
    cudaGetSymbolAddress(&p, g_esrc);   esrc   = (int*)p;
    cudaGetSymbolAddress(&p, g_enorm);  enorm  = (float*)p;
    cudaGetSymbolAddress(&p, g_bufA);   hA     = (__half*)p;
    cudaGetSymbolAddress(&p, g_bufB);   hB     = (__half*)p;
    cudaGetSymbolAddress(&p, g_bufT);   bufT   = (__half*)p;
    cudaGetSymbolAddress(&p, g_wimg);   wimg   = (__half*)p;

    int nb = (n + 1023) / 1024;

    // ---- W prep (independent) + graph normalization + CSR build ----
    k_wprep<<<28, 256>>>(W1, Wm1, Wm2, W2, wimg);
    cudaMemsetAsync(indeg, 0, n * sizeof(int));
    k_deg_count<<<(E + 255) / 256, 256>>>(ei, indeg, E);
    k_scan1<<<nb, 1024>>>(indeg, rowptr, bsum, dinv, n);
    k_scan2<<<1, 1024>>>(bsum, nb);
    k_scan3<<<nb, 1024>>>(rowptr, bsum, cursor, n, E + n);
    k_fill<<<(E + n + 255) / 256, 256>>>(ei, E, n, dinv, cursor, esrc, enorm);

    int gblocks = (n + 127) / 128;
    int ggrid = gblocks < 148 ? gblocks : 148;
    int agg_blocks = (n * 32 + 255) / 256;
    const int SMEM128 = 1024 + 2 * 128 * 128 * 2;  // 66560
    const int SMEM64  = 1024 + 2 * 64 * 128 * 2;   // 33792
    cudaFuncSetAttribute(k_gemm_f32<128>, cudaFuncAttributeMaxDynamicSharedMemorySize, SMEM128);
    cudaFuncSetAttribute(k_gemm_f16<128>, cudaFuncAttributeMaxDynamicSharedMemorySize, SMEM128);
    cudaFuncSetAttribute(k_gemm_f16<64>,  cudaFuncAttributeMaxDynamicSharedMemorySize, SMEM64);

    // ---- layer 1 (fp32 input) ----
    k_gemm_f32<128><<<ggrid, 256, SMEM128>>>(x, wimg, W1, bufT, n);
    k_agg128h<<<agg_blocks, 256>>>(bufT, rowptr, esrc, enorm, b1, hA, n);
    // ---- layer 2 ----
    k_gemm_f16<128><<<ggrid, 256, SMEM128>>>(hA, wimg + 32768, Wm1, bufT, n);
    k_agg128h<<<agg_blocks, 256>>>(bufT, rowptr, esrc, enorm, bm1, hB, n);
    // ---- layer 3 ----
    k_gemm_f16<128><<<ggrid, 256, SMEM128>>>(hB, wimg + 65536, Wm2, bufT, n);
    k_agg128h<<<agg_blocks, 256>>>(bufT, rowptr, esrc, enorm, bm2, hA, n);
    // ---- layer 4 (64 out, fp32 out, no relu) ----
    k_gemm_f16<64><<<ggrid, 256, SMEM64>>>(hA, wimg + 98304, W2, bufT, n);
    k_agg64h<<<agg_blocks, 256>>>(bufT, rowptr, esrc, enorm, b2, (float*)d_out, n);
}

// round 16
// speedup vs baseline: 1.0241x; 1.0241x over previous
#include <cuda_runtime.h>
#include <cuda_fp16.h>
#include <cstdint>
#include <cstddef>

#define NMAX 100000
#define EMAX 1600000
#define TOTMAX (EMAX + NMAX)

#if defined(__CUDA_ARCH_FEAT_SM103_ALL) || defined(__CUDA_ARCH_FEAT_SM100_ALL) || \
    defined(__CUDA_ARCH_FEAT_SM101_ALL)
#define HAS_TCGEN05 1
#else
#define HAS_TCGEN05 0
#endif

// ---------------- device scratch ----------
__device__ int    g_indeg[NMAX];
__device__ float  g_dinv[NMAX];
__device__ int    g_rowptr[NMAX + 1];
__device__ int    g_cursor[NMAX];
__device__ int    g_bsum[1024];
__device__ int    g_esrc[TOTMAX];
__device__ float  g_enorm[TOTMAX];
__device__ __half g_bufA[(size_t)NMAX * 128];
__device__ __half g_bufB[(size_t)NMAX * 128];
__device__ __half g_bufT[(size_t)NMAX * 128];

// ---------------- PTX helpers ----------------
__device__ __forceinline__ uint32_t smem_u32(const void* p) {
    uint32_t a;
    asm("{ .reg .u64 t; cvta.to.shared.u64 t, %1; cvt.u32.u64 %0, t; }" : "=r"(a) : "l"(p));
    return a;
}

#if HAS_TCGEN05
__device__ __forceinline__ uint32_t elect_one() {
    uint32_t pred;
    asm volatile("{\n .reg .pred p;\n elect.sync _|p, 0xFFFFFFFF;\n selp.b32 %0, 1, 0, p;\n}"
                 : "=r"(pred));
    return pred;
}
#define TC_ALLOC(smem_addr, ncols) \
    asm volatile("tcgen05.alloc.cta_group::1.sync.aligned.shared::cta.b32 [%0], %1;" \
                 :: "r"(smem_addr), "r"(ncols) : "memory")
#define TC_DEALLOC(tmem, ncols) \
    asm volatile("tcgen05.dealloc.cta_group::1.sync.aligned.b32 %0, %1;" :: "r"(tmem), "r"(ncols))
#define TC_COMMIT(mbar) \
    asm volatile("tcgen05.commit.cta_group::1.mbarrier::arrive::one.shared::cluster.b64 [%0];" \
                 :: "r"(mbar) : "memory")
#define TC_WAIT_LD() asm volatile("tcgen05.wait::ld.sync.aligned;" ::: "memory")
#define TC_WAIT_ST() asm volatile("tcgen05.wait::st.sync.aligned;" ::: "memory")
#define TC_FENCE_BEFORE() asm volatile("tcgen05.fence::before_thread_sync;" ::: "memory")
#define TC_FENCE_AFTER() asm volatile("tcgen05.fence::after_thread_sync;" ::: "memory")
#define FENCE_ASYNC_SHARED() asm volatile("fence.proxy.async.shared::cta;" ::: "memory")
#define MBAR_INIT(mbar, cnt) \
    asm volatile("mbarrier.init.shared.b64 [%0], %1;" :: "r"(mbar), "r"(cnt) : "memory")
#define MBAR_INVAL(mbar) \
    asm volatile("mbarrier.inval.shared.b64 [%0];" :: "r"(mbar) : "memory")

__device__ __forceinline__ void mbar_wait(uint32_t mbar, uint32_t parity) {
    asm volatile(
        "{\n .reg .pred P1;\n"
        "WAIT_LOOP_%=:\n"
        " mbarrier.try_wait.parity.acquire.cta.shared::cta.b64 P1, [%0], %1, 0x989680;\n"
        " @P1 bra.uni WAIT_DONE_%=;\n"
        " bra.uni WAIT_LOOP_%=;\n"
        "WAIT_DONE_%=:\n}"
        :: "r"(mbar), "r"(parity) : "memory");
}

__device__ __forceinline__ void mma_f16_rs(uint32_t d, uint32_t a_tmem, uint64_t b,
                                           uint32_t idesc, uint32_t en) {
    uint32_t z = 0;
    asm volatile(
        "{\n .reg .pred p;\n setp.ne.u32 p, %5, 0;\n"
        " tcgen05.mma.cta_group::1.kind::f16 [%0], [%1], %2, %3, {%4, %4, %4, %4}, p;\n}"
        :: "r"(d), "r"(a_tmem), "l"(b), "r"(idesc), "r"(z), "r"(en) : "memory");
}

#define LDTM_X32(r, addr) \
    asm volatile( \
        "tcgen05.ld.sync.aligned.32x32b.x32.b32 " \
        "{%0, %1, %2, %3, %4, %5, %6, %7, %8, %9, %10, %11, %12, %13, %14, %15, " \
        " %16, %17, %18, %19, %20, %21, %22, %23, %24, %25, %26, %27, %28, %29, %30, %31}, [%32];" \
        : "=r"((r)[0]),  "=r"((r)[1]),  "=r"((r)[2]),  "=r"((r)[3]), \
          "=r"((r)[4]),  "=r"((r)[5]),  "=r"((r)[6]),  "=r"((r)[7]), \
          "=r"((r)[8]),  "=r"((r)[9]),  "=r"((r)[10]), "=r"((r)[11]), \
          "=r"((r)[12]), "=r"((r)[13]), "=r"((r)[14]), "=r"((r)[15]), \
          "=r"((r)[16]), "=r"((r)[17]), "=r"((r)[18]), "=r"((r)[19]), \
          "=r"((r)[20]), "=r"((r)[21]), "=r"((r)[22]), "=r"((r)[23]), \
          "=r"((r)[24]), "=r"((r)[25]), "=r"((r)[26]), "=r"((r)[27]), \
          "=r"((r)[28]), "=r"((r)[29]), "=r"((r)[30]), "=r"((r)[31]) \
        : "r"(addr))

#define STTM_X32(addr, r) \
    asm volatile( \
        "tcgen05.st.sync.aligned.32x32b.x32.b32 [%0], " \
        "{%1, %2, %3, %4, %5, %6, %7, %8, " \
        " %9, %10, %11, %12, %13, %14, %15, %16, " \
        " %17, %18, %19, %20, %21, %22, %23, %24, " \
        " %25, %26, %27, %28, %29, %30, %31, %32};" \
        :: "r"(addr), \
           "r"((r)[0]),  "r"((r)[1]),  "r"((r)[2]),  "r"((r)[3]), \
           "r"((r)[4]),  "r"((r)[5]),  "r"((r)[6]),  "r"((r)[7]), \
           "r"((r)[8]),  "r"((r)[9]),  "r"((r)[10]), "r"((r)[11]), \
           "r"((r)[12]), "r"((r)[13]), "r"((r)[14]), "r"((r)[15]), \
           "r"((r)[16]), "r"((r)[17]), "r"((r)[18]), "r"((r)[19]), \
           "r"((r)[20]), "r"((r)[21]), "r"((r)[22]), "r"((r)[23]), \
           "r"((r)[24]), "r"((r)[25]), "r"((r)[26]), "r"((r)[27]), \
           "r"((r)[28]), "r"((r)[29]), "r"((r)[30]), "r"((r)[31]) \
        : "memory")

#define STTM_X64(addr, r) \
    asm volatile( \
        "tcgen05.st.sync.aligned.32x32b.x64.b32 [%0], " \
        "{%1, %2, %3, %4, %5, %6, %7, %8, " \
        " %9, %10, %11, %12, %13, %14, %15, %16, " \
        " %17, %18, %19, %20, %21, %22, %23, %24, " \
        " %25, %26, %27, %28, %29, %30, %31, %32, " \
        " %33, %34, %35, %36, %37, %38, %39, %40, " \
        " %41, %42, %43, %44, %45, %46, %47, %48, " \
        " %49, %50, %51, %52, %53, %54, %55, %56, " \
        " %57, %58, %59, %60, %61, %62, %63, %64};" \
        :: "r"(addr), \
           "r"((r)[0]),  "r"((r)[1]),  "r"((r)[2]),  "r"((r)[3]), \
           "r"((r)[4]),  "r"((r)[5]),  "r"((r)[6]),  "r"((r)[7]), \
           "r"((r)[8]),  "r"((r)[9]),  "r"((r)[10]), "r"((r)[11]), \
           "r"((r)[12]), "r"((r)[13]), "r"((r)[14]), "r"((r)[15]), \
           "r"((r)[16]), "r"((r)[17]), "r"((r)[18]), "r"((r)[19]), \
           "r"((r)[20]), "r"((r)[21]), "r"((r)[22]), "r"((r)[23]), \
           "r"((r)[24]), "r"((r)[25]), "r"((r)[26]), "r"((r)[27]), \
           "r"((r)[28]), "r"((r)[29]), "r"((r)[30]), "r"((r)[31]), \
           "r"((r)[32]), "r"((r)[33]), "r"((r)[34]), "r"((r)[35]), \
           "r"((r)[36]), "r"((r)[37]), "r"((r)[38]), "r"((r)[39]), \
           "r"((r)[40]), "r"((r)[41]), "r"((r)[42]), "r"((r)[43]), \
           "r"((r)[44]), "r"((r)[45]), "r"((r)[46]), "r"((r)[47]), \
           "r"((r)[48]), "r"((r)[49]), "r"((r)[50]), "r"((r)[51]), \
           "r"((r)[52]), "r"((r)[53]), "r"((r)[54]), "r"((r)[55]), \
           "r"((r)[56]), "r"((r)[57]), "r"((r)[58]), "r"((r)[59]), \
           "r"((r)[60]), "r"((r)[61]), "r"((r)[62]), "r"((r)[63]) \
        : "memory")

__device__ __forceinline__ uint64_t make_desc(uint32_t addr) {
    const uint64_t base = (uint64_t(2) << 61) | (uint64_t(1) << 46) |
                          (uint64_t(64) << 32) | (uint64_t(1) << 16);
    return base | ((uint64_t)(addr >> 4) & 0x3FFF);
}
#endif  // HAS_TCGEN05

// ---------------- degree count ----------------
__global__ void k_deg_count(const int* __restrict__ ei, int* indeg, int E) {
    int g = blockIdx.x * blockDim.x + threadIdx.x;
    if (g < E) atomicAdd(&indeg[ei[E + g]], 1);
}

// ---------------- scan1 (+ fused dinv) ----------
__global__ void k_scan1(const int* __restrict__ in, int* out, int* bsum,
                        float* dinv, int n) {
    __shared__ int warp_sums[32];
    int g = blockIdx.x * 1024 + threadIdx.x;
    int lane = threadIdx.x & 31;
    int wid = threadIdx.x >> 5;
    int v = 0;
    if (g < n) {
        v = in[g] + 1;
        dinv[g] = rsqrtf((float)v);
    }
    int x = v;
#pragma unroll
    for (int off = 1; off < 32; off <<= 1) {
        int t = __shfl_up_sync(0xFFFFFFFF, x, off);
        if (lane >= off) x += t;
    }
    if (lane == 31) warp_sums[wid] = x;
    __syncthreads();
    if (wid == 0) {
        int s = (lane < 32) ? warp_sums[lane] : 0;
#pragma unroll
        for (int off = 1; off < 32; off <<= 1) {
            int t = __shfl_up_sync(0xFFFFFFFF, s, off);
            if (lane >= off) s += t;
        }
        warp_sums[lane] = s;
    }
    __syncthreads();
    int wbase = (wid > 0) ? warp_sums[wid - 1] : 0;
    if (g < n) out[g] = wbase + x - v;
    if (threadIdx.x == 1023) bsum[blockIdx.x] = wbase + x;
}

// ---------------- fused scan2+scan3: each block reduces its own prefix ----
__global__ void k_scan23(int* rowptr, const int* __restrict__ bsum, int* cursor,
                         int n, int total) {
    __shared__ int red[32];
    int tid = threadIdx.x;
    int lane = tid & 31;
    int wid = tid >> 5;
    // sum of bsum[0 .. blockIdx.x-1]  (blockIdx.x <= 97 < 1024)
    int v = (tid < blockIdx.x) ? bsum[tid] : 0;
#pragma unroll
    for (int o = 16; o; o >>= 1) v += __shfl_down_sync(0xFFFFFFFF, v, o);
    if (lane == 0) red[wid] = v;
    __syncthreads();
    if (wid == 0) {
        int s = (lane < 32) ? red[lane] : 0;
#pragma unroll
        for (int o = 16; o; o >>= 1) s += __shfl_down_sync(0xFFFFFFFF, s, o);
        if (lane == 0) red[0] = s;
    }
    __syncthreads();
    int base = red[0];
    int g = blockIdx.x * 1024 + tid;
    if (g < n) {
        int r = rowptr[g] + base;
        rowptr[g] = r;
        cursor[g] = r;
    }
    if (g == 0) rowptr[n] = total;
}

// ---------------- CSR fill ----------------
__global__ void k_fill(const int* __restrict__ ei, int E, int n,
                       const float* __restrict__ dinv, int* cursor,
                       int* esrc, float* enorm) {
    int g = blockIdx.x * blockDim.x + threadIdx.x;
    if (g < E) {
        int s = ei[g];
        int d = ei[E + g];
        int pos = atomicAdd(&cursor[d], 1);
        esrc[pos] = s;
        enorm[pos] = dinv[s] * dinv[d];
    } else if (g < E + n) {
        int i = g - E;
        int pos = atomicAdd(&cursor[i], 1);
        esrc[pos] = i;
        float dv = dinv[i];
        enorm[pos] = dv * dv;
    }
}

#if HAS_TCGEN05
template <int FOUT>
__device__ __forceinline__ void gemm_epilogue(uint32_t tm_d, int bm, int wid, int lane,
                                              __half* __restrict__ C, int n) {
    int row = bm + wid * 32 + lane;
    for (int c0 = 0; c0 < FOUT; c0 += 32) {
        uint32_t r[32];
        LDTM_X32(r, tm_d + c0);
        TC_WAIT_LD();
        if (row < n) {
            __half* dst = &C[(size_t)row * FOUT + c0];
            uint32_t o[16];
#pragma unroll
            for (int j = 0; j < 16; j++) {
                __half2 hp = __halves2half2(
                    __float2half_rn(__uint_as_float(r[2 * j])),
                    __float2half_rn(__uint_as_float(r[2 * j + 1])));
                o[j] = *reinterpret_cast<uint32_t*>(&hp);
            }
#pragma unroll
            for (int j = 0; j < 4; j++)
                *(uint4*)(dst + j * 8) =
                    make_uint4(o[4 * j], o[4 * j + 1], o[4 * j + 2], o[4 * j + 3]);
        }
    }
    TC_FENCE_BEFORE();
}
#endif

// ---------------- GEMM #1: fp32 input, 3-term fp16 split (layer 1) --------
template <int FOUT>
__global__ void __launch_bounds__(256, 1) __cluster_dims__(1, 1, 1) k_gemm_f32(
    const float* __restrict__ A, const float* __restrict__ W,
    __half* __restrict__ C, int n) {
#if HAS_TCGEN05
    extern __shared__ char smem[];
    constexpr int BH_OFF = 1024;
    constexpr int BL_OFF = BH_OFF + FOUT * 128 * 2;
    constexpr uint32_t IDESC = (1u << 4) | ((FOUT / 8) << 17) | (8u << 24);

    uint32_t sbase = smem_u32(smem);
    int tid = threadIdx.x;
    int wid = tid >> 5;
    int lane = tid & 31;

    if (wid == 0) TC_ALLOC(sbase, 512);
    if (tid == 0) { MBAR_INIT(sbase + 8, 1); MBAR_INIT(sbase + 16, 1); }
    __syncthreads();
    uint32_t tmem;
    asm volatile("ld.shared.b32 %0, [%1];" : "=r"(tmem) : "r"(sbase));

    for (int g = tid; g < FOUT * 16; g += 256) {
        int r = g >> 4;
        int k8 = (g & 15) << 3;
        uint32_t hu[4], lu[4];
#pragma unroll
        for (int j = 0; j < 4; j++) {
            float x0 = W[(size_t)(k8 + 2 * j) * FOUT + r];
            float x1 = W[(size_t)(k8 + 2 * j + 1) * FOUT + r];
            __half h0 = __float2half_rn(x0);
            __half h1 = __float2half_rn(x1);
            float l0 = x0 - __half2float(h0);
            float l1 = x1 - __half2float(h1);
            __half2 hp = __halves2half2(h0, h1);
            __half2 lp = __halves2half2(__float2half_rn(l0), __float2half_rn(l1));
            hu[j] = *reinterpret_cast<uint32_t*>(&hp);
            lu[j] = *reinterpret_cast<uint32_t*>(&lp);
        }
        int atom = (r >> 3) + (k8 >> 6) * (FOUT >> 3);
        uint32_t boff = atom * 1024 + (r & 7) * 128 + (k8 & 63) * 2;
        uint32_t sw = boff ^ ((boff >> 3) & 0x70);
        *(uint4*)(smem + BH_OFF + sw) = make_uint4(hu[0], hu[1], hu[2], hu[3]);
        *(uint4*)(smem + BL_OFF + sw) = make_uint4(lu[0], lu[1], lu[2], lu[3]);
    }
    FENCE_ASYNC_SHARED();
    __syncthreads();

    uint64_t bh = make_desc(sbase + BH_OFF);
    uint64_t bl = make_desc(sbase + BL_OFF);
    const uint64_t BCOL = (uint64_t)FOUT * 8;

    int it = 0;
    int prev_bm = 0;
    for (int tile = blockIdx.x; tile * 128 < n; tile += gridDim.x, it++) {
        int p = it & 1;
        int bm = tile * 128;
        uint32_t tm_a = tmem + p * 128;
        uint32_t tm_d = tmem + 256 + p * 128;

        if (tid >= 128) {
            int wg_tid = tid - 128;
            int row = bm + wg_tid;
            const float4* a4 = (const float4*)&A[(size_t)row * 128];
            uint32_t warp_off = (wg_tid >> 5) << 21;
#pragma unroll
            for (int h = 0; h < 2; h++) {
                float4 f[16];
#pragma unroll
                for (int i = 0; i < 16; i++)
                    f[i] = (row < n) ? a4[h * 16 + i] : make_float4(0.f, 0.f, 0.f, 0.f);
                uint32_t v[32];
#pragma unroll
                for (int i = 0; i < 16; i++) {
                    __half2 p0 = __halves2half2(__float2half_rn(f[i].x),
                                                __float2half_rn(f[i].y));
                    __half2 p1 = __halves2half2(__float2half_rn(f[i].z),
                                                __float2half_rn(f[i].w));
                    v[2 * i]     = *reinterpret_cast<uint32_t*>(&p0);
                    v[2 * i + 1] = *reinterpret_cast<uint32_t*>(&p1);
                }
                STTM_X32(tm_a + h * 32 + warp_off, v);
                TC_WAIT_ST();
#pragma unroll
                for (int i = 0; i < 16; i++) {
                    float lx = f[i].x - __half2float(__float2half_rn(f[i].x));
                    float ly = f[i].y - __half2float(__float2half_rn(f[i].y));
                    float lz = f[i].z - __half2float(__float2half_rn(f[i].z));
                    float lw = f[i].w - __half2float(__float2half_rn(f[i].w));
                    __half2 p0 = __halves2half2(__float2half_rn(lx), __float2half_rn(ly));
                    __half2 p1 = __halves2half2(__float2half_rn(lz), __float2half_rn(lw));
                    v[2 * i]     = *reinterpret_cast<uint32_t*>(&p0);
                    v[2 * i + 1] = *reinterpret_cast<uint32_t*>(&p1);
                }
                STTM_X32(tm_a + 64 + h * 32 + warp_off, v);
                TC_WAIT_ST();
            }
            TC_FENCE_BEFORE();
        } else if (it > 0) {
            int q = p ^ 1;
            mbar_wait(sbase + 8 + 8 * q, ((it - 1) >> 1) & 1);
            TC_FENCE_AFTER();
            gemm_epilogue<FOUT>(tmem + 256 + q * 128, prev_bm, wid, lane, C, n);
        }
        __syncthreads();

        if (wid == 0) {
            TC_FENCE_AFTER();
            if (elect_one()) {
#pragma unroll
                for (int t = 0; t < 3; t++) {
                    uint32_t a_base = tm_a + ((t == 2) ? 64 : 0);
                    uint64_t b_base = (t == 1) ? bl : bh;
#pragma unroll
                    for (int k = 0; k < 8; k++) {
                        uint64_t bd = b_base + ((k < 4) ? (uint64_t)(k * 2)
                                                        : BCOL + (uint64_t)((k - 4) * 2));
                        mma_f16_rs(tm_d, a_base + k * 8, bd, IDESC,
                                   (t > 0 || k > 0) ? 1u : 0u);
                    }
                }
                TC_COMMIT(sbase + 8 + 8 * p);
            }
        }
        prev_bm = bm;
    }
    if (it > 0 && wid < 4) {
        int q = (it - 1) & 1;
        mbar_wait(sbase + 8 + 8 * q, ((it - 1) >> 1) & 1);
        TC_FENCE_AFTER();
        gemm_epilogue<FOUT>(tmem + 256 + q * 128, prev_bm, wid, lane, C, n);
    }
    __syncthreads();
    if (tid == 0) { MBAR_INVAL(sbase + 8); MBAR_INVAL(sbase + 16); }
    __syncthreads();
    if (wid == 0) TC_DEALLOC(tmem, 512);
#else
    int tid = threadIdx.x;
    for (int tile = blockIdx.x; tile * 128 < n; tile += gridDim.x) {
        int bm = tile * 128;
        for (int idx = tid; idx < 128 * FOUT; idx += 256) {
            int r = bm + idx / FOUT, c = idx % FOUT;
            if (r < n) {
                float acc = 0.f;
                for (int k = 0; k < 128; k++)
                    acc += A[(size_t)r * 128 + k] * W[(size_t)k * FOUT + c];
                C[(size_t)r * FOUT + c] = __float2half_rn(acc);
            }
        }
    }
#endif
}

// ---------------- GEMM #2: fp16 input, 2-term (layers 2..4) ----------------
template <int FOUT>
__global__ void __launch_bounds__(256, 1) __cluster_dims__(1, 1, 1) k_gemm_f16(
    const __half* __restrict__ A, const float* __restrict__ W,
    __half* __restrict__ C, int n) {
#if HAS_TCGEN05
    extern __shared__ char smem[];
    constexpr int BH_OFF = 1024;
    constexpr int BL_OFF = BH_OFF + FOUT * 128 * 2;
    constexpr uint32_t IDESC = (1u << 4) | ((FOUT / 8) << 17) | (8u << 24);

    uint32_t sbase = smem_u32(smem);
    int tid = threadIdx.x;
    int wid = tid >> 5;
    int lane = tid & 31;

    if (wid == 0) TC_ALLOC(sbase, 512);
    if (tid == 0) { MBAR_INIT(sbase + 8, 1); MBAR_INIT(sbase + 16, 1); }
    __syncthreads();
    uint32_t tmem;
    asm volatile("ld.shared.b32 %0, [%1];" : "=r"(tmem) : "r"(sbase));

    for (int g = tid; g < FOUT * 16; g += 256) {
        int r = g >> 4;
        int k8 = (g & 15) << 3;
        uint32_t hu[4], lu[4];
#pragma unroll
        for (int j = 0; j < 4; j++) {
            float x0 = W[(size_t)(k8 + 2 * j) * FOUT + r];
            float x1 = W[(size_t)(k8 + 2 * j + 1) * FOUT + r];
            __half h0 = __float2half_rn(x0);
            __half h1 = __float2half_rn(x1);
            float l0 = x0 - __half2float(h0);
            float l1 = x1 - __half2float(h1);
            __half2 hp = __halves2half2(h0, h1);
            __half2 lp = __halves2half2(__float2half_rn(l0), __float2half_rn(l1));
            hu[j] = *reinterpret_cast<uint32_t*>(&hp);
            lu[j] = *reinterpret_cast<uint32_t*>(&lp);
        }
        int atom = (r >> 3) + (k8 >> 6) * (FOUT >> 3);
        uint32_t boff = atom * 1024 + (r & 7) * 128 + (k8 & 63) * 2;
        uint32_t sw = boff ^ ((boff >> 3) & 0x70);
        *(uint4*)(smem + BH_OFF + sw) = make_uint4(hu[0], hu[1], hu[2], hu[3]);
        *(uint4*)(smem + BL_OFF + sw) = make_uint4(lu[0], lu[1], lu[2], lu[3]);
    }
    FENCE_ASYNC_SHARED();
    __syncthreads();

    uint64_t bh = make_desc(sbase + BH_OFF);
    uint64_t bl = make_desc(sbase + BL_OFF);
    const uint64_t BCOL = (uint64_t)FOUT * 8;

    int it = 0;
    int prev_bm = 0;
    for (int tile = blockIdx.x; tile * 128 < n; tile += gridDim.x, it++) {
        int p = it & 1;
        int bm = tile * 128;
        uint32_t tm_a = tmem + p * 64;
        uint32_t tm_d = tmem + 256 + p * 128;

        if (tid >= 128) {
            int wg_tid = tid - 128;
            int row = bm + wg_tid;
            const uint4* a4 = (const uint4*)&A[(size_t)row * 128];
            uint32_t v[64];
#pragma unroll
            for (int i = 0; i < 16; i++) {
                uint4 u = (row < n) ? a4[i] : make_uint4(0, 0, 0, 0);
                v[4 * i] = u.x; v[4 * i + 1] = u.y; v[4 * i + 2] = u.z; v[4 * i + 3] = u.w;
            }
            uint32_t warp_off = (wg_tid >> 5) << 21;
            STTM_X64(tm_a + warp_off, v);
            TC_WAIT_ST();
            TC_FENCE_BEFORE();
        } else if (it > 0) {
            int q = p ^ 1;
            mbar_wait(sbase + 8 + 8 * q, ((it - 1) >> 1) & 1);
            TC_FENCE_AFTER();
            gemm_epilogue<FOUT>(tmem + 256 + q * 128, prev_bm, wid, lane, C, n);
        }
        __syncthreads();

        if (wid == 0) {
            TC_FENCE_AFTER();
            if (elect_one()) {
#pragma unroll
                for (int t = 0; t < 2; t++) {
                    uint64_t b_base = (t == 1) ? bl : bh;
#pragma unroll
                    for (int k = 0; k < 8; k++) {
                        uint64_t bd = b_base + ((k < 4) ? (uint64_t)(k * 2)
                                                        : BCOL + (uint64_t)((k - 4) * 2));
                        mma_f16_rs(tm_d, tm_a + k * 8, bd, IDESC,
                                   (t > 0 || k > 0) ? 1u : 0u);
                    }
                }
                TC_COMMIT(sbase + 8 + 8 * p);
            }
        }
        prev_bm = bm;
    }
    if (it > 0 && wid < 4) {
        int q = (it - 1) & 1;
        mbar_wait(sbase + 8 + 8 * q, ((it - 1) >> 1) & 1);
        TC_FENCE_AFTER();
        gemm_epilogue<FOUT>(tmem + 256 + q * 128, prev_bm, wid, lane, C, n);
    }
    __syncthreads();
    if (tid == 0) { MBAR_INVAL(sbase + 8); MBAR_INVAL(sbase + 16); }
    __syncthreads();
    if (wid == 0) TC_DEALLOC(tmem, 512);
#else
    int tid = threadIdx.x;
    for (int tile = blockIdx.x; tile * 128 < n; tile += gridDim.x) {
        int bm = tile * 128;
        for (int idx = tid; idx < 128 * FOUT; idx += 256) {
            int r = bm + idx / FOUT, c = idx % FOUT;
            if (r < n) {
                float acc = 0.f;
                for (int k = 0; k < 128; k++)
                    acc += __half2float(A[(size_t)r * 128 + k]) * W[(size_t)k * FOUT + c];
                C[(size_t)r * FOUT + c] = __float2half_rn(acc);
            }
        }
    }
#endif
}

// ---------------- aggregation: 8-edge unroll, vector index loads ----------
__global__ void k_agg128h(const __half* __restrict__ t, const int* __restrict__ rowptr,
                          const int* __restrict__ esrc, const float* __restrict__ enorm,
                          const float* __restrict__ bias, __half* __restrict__ out,
                          int n) {
    int w = (blockIdx.x * blockDim.x + threadIdx.x) >> 5;
    if (w >= n) return;
    int lane = threadIdx.x & 31;
    int beg = rowptr[w], end = rowptr[w + 1];
    float ax = 0.f, ay = 0.f, az = 0.f, aw = 0.f;
    int e = beg;
    for (; e < end && (e & 3); e++) {
        int s0 = esrc[e];
        float n0 = enorm[e];
        uint2 u0 = *(const uint2*)&t[(size_t)s0 * 128 + lane * 4];
        float2 a0 = __half22float2(*reinterpret_cast<__half2*>(&u0.x));
        float2 b0 = __half22float2(*reinterpret_cast<__half2*>(&u0.y));
        ax += a0.x * n0; ay += a0.y * n0; az += b0.x * n0; aw += b0.y * n0;
    }
    for (; e + 7 < end; e += 8) {
        int4 s4a = *(const int4*)&esrc[e];
        int4 s4b = *(const int4*)&esrc[e + 4];
        float4 n4a = *(const float4*)&enorm[e];
        float4 n4b = *(const float4*)&enorm[e + 4];
        uint2 u0 = *(const uint2*)&t[(size_t)s4a.x * 128 + lane * 4];
        uint2 u1 = *(const uint2*)&t[(size_t)s4a.y * 128 + lane * 4];
        uint2 u2 = *(const uint2*)&t[(size_t)s4a.z * 128 + lane * 4];
        uint2 u3 = *(const uint2*)&t[(size_t)s4a.w * 128 + lane * 4];
        uint2 u4 = *(const uint2*)&t[(size_t)s4b.x * 128 + lane * 4];
        uint2 u5 = *(const uint2*)&t[(size_t)s4b.y * 128 + lane * 4];
        uint2 u6 = *(const uint2*)&t[(size_t)s4b.z * 128 + lane * 4];
        uint2 u7 = *(const uint2*)&t[(size_t)s4b.w * 128 + lane * 4];
#define ACC(u, nn)                                                             \
        {                                                                      \
            float2 _a = __half22float2(*reinterpret_cast<__half2*>(&(u).x));   \
            float2 _b = __half22float2(*reinterpret_cast<__half2*>(&(u).y));   \
            ax += _a.x * (nn); ay += _a.y * (nn);                              \
            az += _b.x * (nn); aw += _b.y * (nn);                              \
        }
        ACC(u0, n4a.x) ACC(u1, n4a.y) ACC(u2, n4a.z) ACC(u3, n4a.w)
        ACC(u4, n4b.x) ACC(u5, n4b.y) ACC(u6, n4b.z) ACC(u7, n4b.w)
#undef ACC
    }
    for (; e < end; e++) {
        int s0 = esrc[e];
        float n0 = enorm[e];
        uint2 u0 = *(const uint2*)&t[(size_t)s0 * 128 + lane * 4];
        float2 a0 = __half22float2(*reinterpret_cast<__half2*>(&u0.x));
        float2 b0 = __half22float2(*reinterpret_cast<__half2*>(&u0.y));
        ax += a0.x * n0; ay += a0.y * n0; az += b0.x * n0; aw += b0.y * n0;
    }
    float4 b4 = *(const float4*)&bias[lane * 4];
    ax = fmaxf(ax + b4.x, 0.f);
    ay = fmaxf(ay + b4.y, 0.f);
    az = fmaxf(az + b4.z, 0.f);
    aw = fmaxf(aw + b4.w, 0.f);
    __half2 h0 = __halves2half2(__float2half_rn(ax), __float2half_rn(ay));
    __half2 h1 = __halves2half2(__float2half_rn(az), __float2half_rn(aw));
    *(uint2*)&out[(size_t)w * 128 + lane * 4] =
        make_uint2(*reinterpret_cast<uint32_t*>(&h0), *reinterpret_cast<uint32_t*>(&h1));
}

__global__ void k_agg64h(const __half* __restrict__ t, const int* __restrict__ rowptr,
                         const int* __restrict__ esrc, const float* __restrict__ enorm,
                         const float* __restrict__ bias, float* __restrict__ out,
                         int n) {
    int w = (blockIdx.x * blockDim.x + threadIdx.x) >> 5;
    if (w >= n) return;
    int lane = threadIdx.x & 31;
    int beg = rowptr[w], end = rowptr[w + 1];
    float ax = 0.f, ay = 0.f;
    int e = beg;
    for (; e < end && (e & 3); e++) {
        int s0 = esrc[e];
        float n0 = enorm[e];
        uint32_t u0 = *(const uint32_t*)&t[(size_t)s0 * 64 + lane * 2];
        float2 a0 = __half22float2(*reinterpret_cast<__half2*>(&u0));
        ax += a0.x * n0; ay += a0.y * n0;
    }
    for (; e + 7 < end; e += 8) {
        int4 s4a = *(const int4*)&esrc[e];
        int4 s4b = *(const int4*)&esrc[e + 4];
        float4 n4a = *(const float4*)&enorm[e];
        float4 n4b = *(const float4*)&enorm[e + 4];
        uint32_t u0 = *(const uint32_t*)&t[(size_t)s4a.x * 64 + lane * 2];
        uint32_t u1 = *(const uint32_t*)&t[(size_t)s4a.y * 64 + lane * 2];
        uint32_t u2 = *(const uint32_t*)&t[(size_t)s4a.z * 64 + lane * 2];
        uint32_t u3 = *(const uint32_t*)&t[(size_t)s4a.w * 64 + lane * 2];
        uint32_t u4 = *(const uint32_t*)&t[(size_t)s4b.x * 64 + lane * 2];
        uint32_t u5 = *(const uint32_t*)&t[(size_t)s4b.y * 64 + lane * 2];
        uint32_t u6 = *(const uint32_t*)&t[(size_t)s4b.z * 64 + lane * 2];
        uint32_t u7 = *(const uint32_t*)&t[(size_t)s4b.w * 64 + lane * 2];
#define ACC(u, nn)                                                             \
        {                                                                      \
            float2 _a = __half22float2(*reinterpret_cast<__half2*>(&(u)));     \
            ax += _a.x * (nn); ay += _a.y * (nn);                              \
        }
        ACC(u0, n4a.x) ACC(u1, n4a.y) ACC(u2, n4a.z) ACC(u3, n4a.w)
        ACC(u4, n4b.x) ACC(u5, n4b.y) ACC(u6, n4b.z) ACC(u7, n4b.w)
#undef ACC
    }
    for (; e < end; e++) {
        int s0 = esrc[e];
        float n0 = enorm[e];
        uint32_t u0 = *(const uint32_t*)&t[(size_t)s0 * 64 + lane * 2];
        float2 a0 = __half22float2(*reinterpret_cast<__half2*>(&u0));
        ax += a0.x * n0; ay += a0.y * n0;
    }
    float2 b2 = *(const float2*)&bias[lane * 2];
    ax += b2.x; ay += b2.y;
    *(float2*)&out[(size_t)w * 64 + lane * 2] = make_float2(ax, ay);
}

// ---------------- host ----------------
extern "C" void kernel_launch(void* const* d_in, const int* in_sizes, int n_in,
                              void* d_out, int out_size) {
    const float* x   = (const float*)d_in[0];
    const int*   ei  = (const int*)d_in[1];
    const float* W1  = (const float*)d_in[2];
    const float* b1  = (const float*)d_in[3];
    const float* Wm1 = (const float*)d_in[4];
    const float* bm1 = (const float*)d_in[5];
    const float* Wm2 = (const float*)d_in[6];
    const float* bm2 = (const float*)d_in[7];
    const float* W2  = (const float*)d_in[8];
    const float* b2  = (const float*)d_in[9];

    int n = in_sizes[0] / 128;
    int E = in_sizes[1] / 2;

    void* p;
    int *indeg, *rowptr, *cursor, *bsum, *esrc;
    float *dinv, *enorm;
    __half *hA, *hB, *bufT;
    cudaGetSymbolAddress(&p, g_indeg);  indeg  = (int*)p;
    cudaGetSymbolAddress(&p, g_dinv);   dinv   = (float*)p;
    cudaGetSymbolAddress(&p, g_rowptr); rowptr = (int*)p;
    cudaGetSymbolAddress(&p, g_cursor); cursor = (int*)p;
    cudaGetSymbolAddress(&p, g_bsum);   bsum   = (int*)p;
    cudaGetSymbolAddress(&p, g_esrc);   esrc   = (int*)p;
    cudaGetSymbolAddress(&p, g_enorm);  enorm  = (float*)p;
    cudaGetSymbolAddress(&p, g_bufA);   hA     = (__half*)p;
    cudaGetSymbolAddress(&p, g_bufB);   hB     = (__half*)p;
    cudaGetSymbolAddress(&p, g_bufT);   bufT   = (__half*)p;

    int nb = (n + 1023) / 1024;

    // ---- graph normalization + CSR build ----
    cudaMemsetAsync(indeg, 0, n * sizeof(int));
    k_deg_count<<<(E + 255) / 256, 256>>>(ei, indeg, E);
    k_scan1<<<nb, 1024>>>(indeg, rowptr, bsum, dinv, n);
    k_scan23<<<nb, 1024>>>(rowptr, bsum, cursor, n, E + n);
    k_fill<<<(E + n + 255) / 256, 256>>>(ei, E, n, dinv, cursor, esrc, enorm);

    int gblocks = (n + 127) / 128;
    int ggrid = gblocks < 148 ? gblocks : 148;
    int agg_blocks = (n * 32 + 255) / 256;
    const int SMEM128 = 1024 + 2 * 128 * 128 * 2;  // 66560
    const int SMEM64  = 1024 + 2 * 64 * 128 * 2;   // 33792
    cudaFuncSetAttribute(k_gemm_f32<128>, cudaFuncAttributeMaxDynamicSharedMemorySize, SMEM128);
    cudaFuncSetAttribute(k_gemm_f16<128>, cudaFuncAttributeMaxDynamicSharedMemorySize, SMEM128);
    cudaFuncSetAttribute(k_gemm_f16<64>,  cudaFuncAttributeMaxDynamicSharedMemorySize, SMEM64);

    // ---- layer 1 (fp32 input) ----
    k_gemm_f32<128><<<ggrid, 256, SMEM128>>>(x, W1, bufT, n);
    k_agg128h<<<agg_blocks, 256>>>(bufT, rowptr, esrc, enorm, b1, hA, n);
    // ---- layer 2 ----
    k_gemm_f16<128><<<ggrid, 256, SMEM128>>>(hA, Wm1, bufT, n);
    k_agg128h<<<agg_blocks, 256>>>(bufT, rowptr, esrc, enorm, bm1, hB, n);
    // ---- layer 3 ----
    k_gemm_f16<128><<<ggrid, 256, SMEM128>>>(hB, Wm2, bufT, n);
    k_agg128h<<<agg_blocks, 256>>>(bufT, rowptr, esrc, enorm, bm2, hA, n);
    // ---- layer 4 (64 out, fp32 out, no relu) ----
    k_gemm_f16<64><<<ggrid, 256, SMEM64>>>(hA, W2, bufT, n);
    k_agg64h<<<agg_blocks, 256>>>(bufT, rowptr, esrc, enorm, b2, (float*)d_out, n);
}